// round 1
// baseline (speedup 1.0000x reference)
#include <cuda_runtime.h>
#include <cuda_bf16.h>
#include <math.h>

// Spherical harmonics Re(Y_l^m), l=0..3, scipy sph_harm convention.
// Output layout: [Y0 (N*1) | Y1 (N*3) | Y2 (N*5) | Y3 (N*7)] — tuple order, each row-major.

// Precomputed N_{l,m} (and merged constant factors):
#define C_Y00   0.28209479177387814f   // sqrt(1/(4pi))
#define C_Y10   0.48860251190291992f   // sqrt(3/(4pi))
#define C_Y11   0.34549414947133547f   // sqrt(3/(8pi))
#define C_Y20   0.31539156525252005f   // 0.5*sqrt(5/(4pi))
#define C_Y21   0.77254840404659256f   // 3*sqrt(5/(24pi))
#define C_Y22   0.38627420202329628f   // 3*sqrt(5/(96pi))
#define C_Y30   0.37317633259011540f   // 0.5*sqrt(7/(4pi))
#define C_Y31   0.32318018411415066f   // 1.5*sqrt(7/(48pi))
#define C_Y32   1.02198547643328236f   // 15*sqrt(7/(480pi))
#define C_Y33   0.41722382363278409f   // 15*sqrt(7/(2880pi))

__global__ void sh_l3_kernel(const float* __restrict__ dirs,
                             float* __restrict__ out, int n) {
    int i = blockIdx.x * blockDim.x + threadIdx.x;
    if (i >= n) return;

    float x = __ldg(&dirs[3 * i + 0]);
    float y = __ldg(&dirs[3 * i + 1]);
    float z = __ldg(&dirs[3 * i + 2]);

    float r   = sqrtf(x * x + y * y + z * z);
    float ct  = z / (r + 1e-8f);
    float ct2 = ct * ct;
    float st  = sqrtf(fmaxf(1.0f - ct2, 0.0f));
    float st2 = st * st;

    // cos(m*phi), phi = atan2(y, x). Chebyshev from c1 = cos(phi).
    float rho2 = x * x + y * y;
    float c1, c2, c3;
    if (rho2 > 0.0f) {
        float inv_rho = rsqrtf(rho2);
        c1 = x * inv_rho;
        c2 = 2.0f * c1 * c1 - 1.0f;       // cos(2 phi)
        c3 = c1 * (2.0f * c2 - 1.0f);     // cos(3 phi)
    } else {
        c1 = 1.0f; c2 = 1.0f; c3 = 1.0f;  // atan2(0,0) = 0
    }

    // l = 0
    out[i] = C_Y00;

    // l = 1: P10 = ct, P11 = -st
    float y10 = C_Y10 * ct;
    float y11 = -C_Y11 * st * c1;
    float* o1 = out + (size_t)n;
    o1[3 * i + 0] = -y11;   // m = -1: (-1)^1 * y11
    o1[3 * i + 1] =  y10;   // m =  0
    o1[3 * i + 2] =  y11;   // m = +1

    // l = 2
    float y20 = C_Y20 * (3.0f * ct2 - 1.0f);
    float y21 = -C_Y21 * ct * st * c1;
    float y22 =  C_Y22 * st2 * c2;
    float* o2 = out + (size_t)4 * n;
    o2[5 * i + 0] =  y22;   // m = -2
    o2[5 * i + 1] = -y21;   // m = -1
    o2[5 * i + 2] =  y20;   // m =  0
    o2[5 * i + 3] =  y21;   // m = +1
    o2[5 * i + 4] =  y22;   // m = +2

    // l = 3
    float y30 =  C_Y30 * ct * (5.0f * ct2 - 3.0f);
    float y31 = -C_Y31 * (5.0f * ct2 - 1.0f) * st * c1;
    float y32 =  C_Y32 * ct * st2 * c2;
    float y33 = -C_Y33 * st * st2 * c3;
    float* o3 = out + (size_t)9 * n;
    o3[7 * i + 0] = -y33;   // m = -3
    o3[7 * i + 1] =  y32;   // m = -2
    o3[7 * i + 2] = -y31;   // m = -1
    o3[7 * i + 3] =  y30;   // m =  0
    o3[7 * i + 4] =  y31;   // m = +1
    o3[7 * i + 5] =  y32;   // m = +2
    o3[7 * i + 6] =  y33;   // m = +3
}

extern "C" void kernel_launch(void* const* d_in, const int* in_sizes, int n_in,
                              void* d_out, int out_size) {
    const float* dirs = (const float*)d_in[0];
    float* out = (float*)d_out;
    int n = in_sizes[0] / 3;

    const int threads = 256;
    int blocks = (n + threads - 1) / threads;
    sh_l3_kernel<<<blocks, threads>>>(dirs, out, n);
}

// round 2
// speedup vs baseline: 1.6349x; 1.6349x over previous
#include <cuda_runtime.h>
#include <cuda_bf16.h>
#include <math.h>

// Spherical harmonics Re(Y_l^m), l=0..3, scipy sph_harm convention.
// Output layout: [Y0 (N*1) | Y1 (N*3) | Y2 (N*5) | Y3 (N*7)].
//
// Strategy: smem-staged compute so that ALL global traffic is contiguous
// float4 loads/stores (minimum L1 wavefronts, full-line writes).

#define C_Y00   0.28209479177387814f
#define C_Y10   0.48860251190291992f
#define C_Y11   0.34549414947133547f
#define C_Y20   0.31539156525252005f
#define C_Y21   0.77254840404659256f
#define C_Y22   0.38627420202329628f
#define C_Y30   0.37317633259011540f
#define C_Y31   0.32318018411415066f
#define C_Y32   1.02198547643328236f
#define C_Y33   0.41722382363278409f

#define THREADS 128
#define PPT     4                    // points per thread
#define PPB     (THREADS * PPT)      // 512 points per block

__global__ __launch_bounds__(THREADS)
void sh_l3_staged_kernel(const float* __restrict__ dirs,
                         float* __restrict__ out, int n) {
    __shared__ float s_in[PPB * 3];   // 6 KB
    __shared__ float s0[PPB];         // 2 KB
    __shared__ float s1[PPB * 3];     // 6 KB
    __shared__ float s2[PPB * 5];     // 10 KB
    __shared__ float s3[PPB * 7];     // 14 KB

    const int tid = threadIdx.x;
    const int bid = blockIdx.x;
    const long long base_pt = (long long)bid * PPB;

    // ---- Phase 0: coalesced float4 load of this block's input slab ----
    {
        const float4* in4 = (const float4*)dirs;
        float4* s_in4 = (float4*)s_in;
        const long long total4 = ((long long)n * 3) >> 2;   // n*3 floats as float4
        const long long base4 = base_pt * 3 / 4;            // PPB*3 = 1536 divisible by 4
        #pragma unroll
        for (int k = 0; k < 3; k++) {
            long long g4 = base4 + tid + k * THREADS;
            if (g4 < total4) s_in4[tid + k * THREADS] = in4[g4];
        }
    }
    __syncthreads();

    // ---- Phase 1: compute 4 points per thread, scatter to smem regions ----
    #pragma unroll
    for (int p = 0; p < PPT; p++) {
        const int lp = tid + p * THREADS;       // stride-1 across loop, stride coprime in smem
        const long long gp = base_pt + lp;
        if (gp >= n) break;

        float x = s_in[lp * 3 + 0];
        float y = s_in[lp * 3 + 1];
        float z = s_in[lp * 3 + 2];

        float r   = sqrtf(x * x + y * y + z * z);
        float ct  = z / (r + 1e-8f);
        float ct2 = ct * ct;
        float st  = sqrtf(fmaxf(1.0f - ct2, 0.0f));
        float st2 = st * st;

        float rho2 = x * x + y * y;
        float c1, c2, c3;
        if (rho2 > 0.0f) {
            float inv_rho = rsqrtf(rho2);
            c1 = x * inv_rho;
            c2 = 2.0f * c1 * c1 - 1.0f;
            c3 = c1 * (2.0f * c2 - 1.0f);
        } else {
            c1 = 1.0f; c2 = 1.0f; c3 = 1.0f;
        }

        // l = 0
        s0[lp] = C_Y00;

        // l = 1
        float y10 = C_Y10 * ct;
        float y11 = -C_Y11 * st * c1;
        s1[lp * 3 + 0] = -y11;
        s1[lp * 3 + 1] =  y10;
        s1[lp * 3 + 2] =  y11;

        // l = 2
        float y20 = C_Y20 * (3.0f * ct2 - 1.0f);
        float y21 = -C_Y21 * ct * st * c1;
        float y22 =  C_Y22 * st2 * c2;
        s2[lp * 5 + 0] =  y22;
        s2[lp * 5 + 1] = -y21;
        s2[lp * 5 + 2] =  y20;
        s2[lp * 5 + 3] =  y21;
        s2[lp * 5 + 4] =  y22;

        // l = 3
        float y30 =  C_Y30 * ct * (5.0f * ct2 - 3.0f);
        float y31 = -C_Y31 * (5.0f * ct2 - 1.0f) * st * c1;
        float y32 =  C_Y32 * ct * st2 * c2;
        float y33 = -C_Y33 * st * st2 * c3;
        s3[lp * 7 + 0] = -y33;
        s3[lp * 7 + 1] =  y32;
        s3[lp * 7 + 2] = -y31;
        s3[lp * 7 + 3] =  y30;
        s3[lp * 7 + 4] =  y31;
        s3[lp * 7 + 5] =  y32;
        s3[lp * 7 + 6] =  y33;
    }
    __syncthreads();

    // ---- Phase 2: coalesced float4 flush of each region ----
    // Region l: global base = out + (l^2)*n, block slab = base_pt*(2l+1) floats.
    {
        const long long nll = n;

        // l = 0: 512 floats = 128 float4, 1 per thread
        {
            float* gbase = out;
            long long fbase = base_pt;            // floats
            long long rem = nll - fbase;          // floats remaining in region
            long long idx = (long long)tid * 4;
            if (idx + 4 <= rem) {
                *(float4*)(gbase + fbase + idx) = ((const float4*)s0)[tid];
            } else {
                for (int e = 0; e < 4; e++)
                    if (idx + e < rem) gbase[fbase + idx + e] = s0[idx + e];
            }
        }
        // l = 1: 1536 floats = 384 float4, 3 per thread
        {
            float* gbase = out + nll;
            long long fbase = base_pt * 3;
            long long rem = nll * 3 - fbase;
            #pragma unroll
            for (int k = 0; k < 3; k++) {
                long long idx = (long long)(tid + k * THREADS) * 4;
                if (idx + 4 <= rem) {
                    *(float4*)(gbase + fbase + idx) = ((const float4*)s1)[tid + k * THREADS];
                } else {
                    for (int e = 0; e < 4; e++)
                        if (idx + e < rem) gbase[fbase + idx + e] = s1[idx + e];
                }
            }
        }
        // l = 2: 2560 floats = 640 float4, 5 per thread
        {
            float* gbase = out + 4 * nll;
            long long fbase = base_pt * 5;
            long long rem = nll * 5 - fbase;
            #pragma unroll
            for (int k = 0; k < 5; k++) {
                long long idx = (long long)(tid + k * THREADS) * 4;
                if (idx + 4 <= rem) {
                    *(float4*)(gbase + fbase + idx) = ((const float4*)s2)[tid + k * THREADS];
                } else {
                    for (int e = 0; e < 4; e++)
                        if (idx + e < rem) gbase[fbase + idx + e] = s2[idx + e];
                }
            }
        }
        // l = 3: 3584 floats = 896 float4, 7 per thread
        {
            float* gbase = out + 9 * nll;
            long long fbase = base_pt * 7;
            long long rem = nll * 7 - fbase;
            #pragma unroll
            for (int k = 0; k < 7; k++) {
                long long idx = (long long)(tid + k * THREADS) * 4;
                if (idx + 4 <= rem) {
                    *(float4*)(gbase + fbase + idx) = ((const float4*)s3)[tid + k * THREADS];
                } else {
                    for (int e = 0; e < 4; e++)
                        if (idx + e < rem) gbase[fbase + idx + e] = s3[idx + e];
                }
            }
        }
    }
}

extern "C" void kernel_launch(void* const* d_in, const int* in_sizes, int n_in,
                              void* d_out, int out_size) {
    const float* dirs = (const float*)d_in[0];
    float* out = (float*)d_out;
    int n = in_sizes[0] / 3;

    int blocks = (n + PPB - 1) / PPB;
    sh_l3_staged_kernel<<<blocks, THREADS>>>(dirs, out, n);
}